// round 15
// baseline (speedup 1.0000x reference)
#include <cuda_runtime.h>
#include <cuda_fp16.h>
#include <cstdint>
#include <math.h>

#define K_DIM 768
#define N_DIM 3072
#define M_MAX 12608
#define NCHUNK 12            // K / 64

// ---------------- device scratch (allocation-free rule) ----------------
__device__ __half g_xq[M_MAX * K_DIM];          // x quantized fp16 [M, K]
// compressed W (fp16): per row, per k64 chunk: 32 halfs = 64B
__device__ __half g_wc[N_DIM * NCHUNK * 32];
__device__ uint32_t g_meta[N_DIM * 24];         // [row][k32 block], nibble q = group q

// ---------------- PTX helpers (base-target safe) ----------------
__device__ __forceinline__ uint32_t smem_u32(const void* p) {
    uint32_t a;
    asm("{ .reg .u64 t; cvta.to.shared.u64 t, %1; cvt.u32.u64 %0, t; }" : "=r"(a) : "l"(p));
    return a;
}
__device__ __forceinline__ void cpasync16(uint32_t dst, const void* src) {
    asm volatile("cp.async.cg.shared.global [%0], [%1], 16;" :: "r"(dst), "l"(src));
}
__device__ __forceinline__ void cpasync8(uint32_t dst, const void* src) {
    asm volatile("cp.async.ca.shared.global [%0], [%1], 8;" :: "r"(dst), "l"(src));
}
#define CP_COMMIT() asm volatile("cp.async.commit_group;" ::: "memory")
__device__ __forceinline__ uint32_t lds32(uint32_t addr) {
    uint32_t v;
    asm volatile("ld.shared.b32 %0, [%1];" : "=r"(v) : "r"(addr));
    return v;
}
__device__ __forceinline__ void sts32(uint32_t addr, float v) {
    asm volatile("st.shared.f32 [%0], %1;" :: "r"(addr), "f"(v));
}
__device__ __forceinline__ float4 lds128(uint32_t addr) {
    float4 v;
    asm volatile("ld.shared.v4.f32 {%0,%1,%2,%3}, [%4];"
                 : "=f"(v.x), "=f"(v.y), "=f"(v.z), "=f"(v.w) : "r"(addr));
    return v;
}
__device__ __forceinline__ void ldsm4(uint32_t* r, uint32_t addr) {
    asm volatile("ldmatrix.sync.aligned.m8n8.x4.shared.b16 {%0,%1,%2,%3}, [%4];"
                 : "=r"(r[0]), "=r"(r[1]), "=r"(r[2]), "=r"(r[3]) : "r"(addr));
}
// sparse MMA fp16: A = m16xk32 2:4 (compressed 4 regs), B = k32xn8 (4 regs)
__device__ __forceinline__ void mma_sp_f16(float* c, const uint32_t* a,
                                           const uint32_t* b, uint32_t e) {
    asm volatile(
        "mma.sp::ordered_metadata.sync.aligned.m16n8k32.row.col.f32.f16.f16.f32 "
        "{%0,%1,%2,%3}, {%4,%5,%6,%7}, {%8,%9,%10,%11}, {%0,%1,%2,%3}, %12, 0x0;"
        : "+f"(c[0]), "+f"(c[1]), "+f"(c[2]), "+f"(c[3])
        : "r"(a[0]), "r"(a[1]), "r"(a[2]), "r"(a[3]),
          "r"(b[0]), "r"(b[1]), "r"(b[2]), "r"(b[3]), "r"(e));
}
__device__ __forceinline__ uint32_t pack_h2(float a, float b) {
    __half2 p(__float2half_rn(a), __float2half_rn(b));
    return *reinterpret_cast<uint32_t*>(&p);
}

// ---------------- kernel 1: 2:4 prune + compress to fp16 + metadata ----------------
__global__ void mask_compress_w(const float* __restrict__ w,
                                __half* __restrict__ wc,
                                uint32_t* __restrict__ meta, int total) {
    int idx = blockIdx.x * blockDim.x + threadIdx.x;
    if (idx >= total) return;                   // total = 3072 * 24
    const int row = idx / 24, kb = idx % 24;
    const float4* src = reinterpret_cast<const float4*>(w + (size_t)row * K_DIM + kb * 32);

    uint32_t hw[8], m = 0;
#pragma unroll
    for (int gq = 0; gq < 8; gq++) {
        float4 q = src[gq];
        float v[4] = {q.x, q.y, q.z, q.w};
        float a[4] = {fabsf(v[0]), fabsf(v[1]), fabsf(v[2]), fabsf(v[3])};
        int p1 = 0;
#pragma unroll
        for (int i = 1; i < 4; i++) if (a[i] < a[p1]) p1 = i;     // stable: strict <
        int p2 = (p1 == 0) ? 1 : 0;
#pragma unroll
        for (int i = 0; i < 4; i++)
            if (i != p1 && i != p2 && a[i] < a[p2]) p2 = i;
        int j0 = -1, j1 = -1;
#pragma unroll
        for (int i = 0; i < 4; i++)
            if (i != p1 && i != p2) { if (j0 < 0) j0 = i; else j1 = i; }
        m |= (uint32_t)(j0 | (j1 << 2)) << (4 * gq);
        hw[gq] = pack_h2(v[j0], v[j1]);
    }
    const int ch = kb >> 1, h = kb & 1;
    __half* dst = wc + ((size_t)row * NCHUNK + ch) * 32 + h * 16;   // 32B-aligned
    uint4* d4 = reinterpret_cast<uint4*>(dst);
    d4[0] = make_uint4(hw[0], hw[1], hw[2], hw[3]);
    d4[1] = make_uint4(hw[4], hw[5], hw[6], hw[7]);
    meta[(size_t)row * 24 + kb] = m;
}

// ---------------- kernel 2: quantize x to fp16 ----------------
__global__ void quant_x(const float* __restrict__ x,
                        __half* __restrict__ xq, int nquads) {
    int g = blockIdx.x * blockDim.x + threadIdx.x;
    if (g >= nquads) return;
    float4 v = reinterpret_cast<const float4*>(x)[g];
    reinterpret_cast<uint2*>(xq)[g] =
        make_uint2(pack_h2(v.x, v.y), pack_h2(v.z, v.w));
}

// ---------------- kernel 3: sparse GEMM  CT[N, M] = Wq(2:4) * XqT, transposed store ----------------
// CTA: 256 features x 128 tokens, 512 threads, occ 1, 4-stage cp.async pipeline.
// Warp layout: 4 feature-warps (64 feats) x 4 token-warps (32 toks) — R11-verified warp shape.
// Halves L2 B-traffic vs 128-feat tiles (grid.x 24 -> 12).
// stage: A(wq) 16K @0 (256 rows x 64B), B 16K @16384 (128 tok x 128B), meta 2K @32768
#define ST_A    0
#define ST_B    16384
#define ST_ME   32768
#define ST_SZ   34816
#define NSTAGE  4
#define SMEM_TOTAL (NSTAGE * ST_SZ)   // 139264 (epilogue scratch 16*8704=139264 fits exactly)
#define EPI_STRIDE 68            // floats per token row (272B: 16B-aligned, conflict-free STS)

__global__ __launch_bounds__(512, 1)
void gemm_sp(const __half* __restrict__ Wc, const uint32_t* __restrict__ Meta,
             const __half* __restrict__ Xq,
             const float* __restrict__ bias, float* __restrict__ C, int M) {
    extern __shared__ char smem[];
    const uint32_t sbase = smem_u32(smem);
    const int tid = threadIdx.x;
    const int wid = tid >> 5, lane = tid & 31;
    const int g = lane >> 2, t4 = lane & 3;
    const int kh = lane & 1;           // meta k-half this thread supplies
    const int i_m = lane >> 3;         // ldmatrix matrix index 0..3
    const int j_m = lane & 7;          // ldmatrix row within matrix
    const int wr = wid & 3;            // feature warp: 64 features
    const int wt = wid >> 2;           // token warp: 32 tokens
    const int bn = blockIdx.x * 256;   // feature tile
    const int bt = blockIdx.y * 128;   // token tile

    auto ld_stage = [&](int t, int s) {
        const uint32_t stg = sbase + s * ST_SZ;
        // A: 16KB, 256 rows x 64B, XOR(r&3) swizzle
#pragma unroll
        for (int j = 0; j < 2; j++) {
            int i = tid + 512 * j;          // 0..1023
            int r = i >> 2, c = i & 3;
            uint32_t sw = (uint32_t)(r * 64 + ((c ^ (r & 3)) << 4));
            cpasync16(stg + ST_A + sw, Wc + ((size_t)(bn + r) * NCHUNK + t) * 32 + c * 8);
        }
        // B: 16KB, 128 tok x 128B, XOR(r&7) swizzle
#pragma unroll
        for (int j = 0; j < 2; j++) {
            int i = tid + 512 * j;          // 0..1023
            int r = i >> 3, c = i & 7;
            uint32_t sw = (uint32_t)(r * 128 + ((c ^ (r & 7)) << 4));
            int tok = bt + r; if (tok > M - 1) tok = M - 1;
            cpasync16(stg + ST_B + sw, Xq + (size_t)tok * K_DIM + t * 64 + c * 8);
        }
        if (tid < 256)
            cpasync8(stg + ST_ME + tid * 8, Meta + (size_t)(bn + tid) * 24 + t * 2);
        CP_COMMIT();
    };

    float acc[4][4][4];
#pragma unroll
    for (int mt = 0; mt < 4; mt++)
#pragma unroll
        for (int nt = 0; nt < 4; nt++)
#pragma unroll
            for (int q = 0; q < 4; q++) acc[mt][nt][q] = 0.0f;

    // prologue: 3 chunks in flight
    ld_stage(0, 0);
    ld_stage(1, 1);
    ld_stage(2, 2);

    for (int t = 0; t < NCHUNK; t++) {
        if (t <= NCHUNK - 3)      asm volatile("cp.async.wait_group 2;" ::: "memory");
        else if (t == NCHUNK - 2) asm volatile("cp.async.wait_group 1;" ::: "memory");
        else                      asm volatile("cp.async.wait_group 0;" ::: "memory");
        // barrier also orders: all warps done computing chunk t-1 before ld_stage below
        // overwrites stage (t+3)&3 == (t-1)&3.
        __syncthreads();

        const uint32_t stg = sbase + (t & (NSTAGE - 1)) * ST_SZ;
#pragma unroll
        for (int h = 0; h < 2; h++) {                 // two k32 steps per chunk
            uint32_t e[4], aq[4][4];
#pragma unroll
            for (int mt = 0; mt < 4; mt++) {
                const int rbase = wr * 64 + mt * 16;
                // metadata (m16n8k32, sel 0): T_even k0..15 / T_odd k16..31 of rows g, g+8
                const uint32_t m_a = lds32(stg + ST_ME + (rbase + g) * 8 + h * 4);
                const uint32_t m_b = lds32(stg + ST_ME + (rbase + g + 8) * 8 + h * 4);
                e[mt] = ((m_a >> (16 * kh)) & 0xFFFFu) | (((m_b >> (16 * kh)) & 0xFFFFu) << 16);
                // A fragment via ldmatrix.x4 (64B rows, 4 octets: step h uses octets 2h, 2h+1)
                const int arow = rbase + ((i_m & 1) << 3) + j_m;
                const int oct = 2 * h + (i_m >> 1);
                ldsm4(aq[mt], stg + ST_A + arow * 64 + (uint32_t)((oct ^ (arow & 3)) << 4));
            }
#pragma unroll
            for (int nt = 0; nt < 4; nt++) {
                // B fragment via ldmatrix.x4: matrix i = k-octet (4h+i) of 8 token rows
                const int tok = wt * 32 + nt * 8 + j_m;
                const uint32_t sw = (uint32_t)(((4 * h + i_m) ^ (tok & 7)) << 4);
                uint32_t bq[4];
                ldsm4(bq, stg + ST_B + tok * 128 + sw);
#pragma unroll
                for (int mt = 0; mt < 4; mt++)
                    mma_sp_f16(acc[mt][nt], aq[mt], bq, e[mt]);
            }
        }
        if (t + 3 < NCHUNK) ld_stage(t + 3, (t + 3) & (NSTAGE - 1));
    }

    // ---- epilogue: bias + smem transpose (CT frag -> C[token][feature]) ----  (R11-verified shape)
    __syncthreads();   // done reading stages; reuse smem
    float bias_v[4][2];
#pragma unroll
    for (int mt = 0; mt < 4; mt++) {
        const int f = bn + wr * 64 + mt * 16 + g;
        bias_v[mt][0] = __ldg(bias + f);
        bias_v[mt][1] = __ldg(bias + f + 8);
    }
    // warp-private region: 32 tokens x EPI_STRIDE floats (8704 B/warp, 139264 total)
    const uint32_t wb = sbase + wid * (32 * EPI_STRIDE * 4);
#pragma unroll
    for (int mt = 0; mt < 4; mt++)
#pragma unroll
        for (int nt = 0; nt < 4; nt++) {
            const int tokL = nt * 8 + 2 * t4;
            const int fL = mt * 16 + g;
            const uint32_t a0 = wb + (uint32_t)(tokL * EPI_STRIDE + fL) * 4;
            sts32(a0,                        acc[mt][nt][0] + bias_v[mt][0]);
            sts32(a0 + EPI_STRIDE * 4,       acc[mt][nt][1] + bias_v[mt][0]);  // token+1
            sts32(a0 + 32,                   acc[mt][nt][2] + bias_v[mt][1]);  // feat+8
            sts32(a0 + EPI_STRIDE * 4 + 32,  acc[mt][nt][3] + bias_v[mt][1]);
        }
    __syncwarp();
#pragma unroll
    for (int it = 0; it < 4; it++) {
        const int tokL = it * 8 + g;
        const int tokG = bt + wt * 32 + tokL;
        if (tokG < M) {
#pragma unroll
            for (int j = 0; j < 4; j++) {
                const int fl = t4 * 4 + j * 16;
                float4 v = lds128(wb + (uint32_t)(tokL * EPI_STRIDE + fl) * 4);
                *reinterpret_cast<float4*>(C + (size_t)tokG * N_DIM + bn + wr * 64 + fl) = v;
            }
        }
    }
}

// ---------------------------------------------------------------------------
extern "C" void kernel_launch(void* const* d_in, const int* in_sizes, int n_in,
                              void* d_out, int out_size) {
    const float* x    = (const float*)d_in[0];  // [M, 768]
    const float* w    = (const float*)d_in[1];  // [3072, 768]
    const float* bias = (const float*)d_in[2];  // [3072]
    float* out        = (float*)d_out;          // [M, 3072]
    (void)n_in; (void)out_size;

    const int M = in_sizes[0] / K_DIM;          // 12608

    __half *xq, *wc;
    uint32_t* meta;
    cudaGetSymbolAddress((void**)&xq, g_xq);
    cudaGetSymbolAddress((void**)&wc, g_wc);
    cudaGetSymbolAddress((void**)&meta, g_meta);

    const int totalW = N_DIM * 24;              // (row, k32 block)
    mask_compress_w<<<(totalW + 255) / 256, 256>>>(w, wc, meta, totalW);
    const int nquads = (M * K_DIM) / 4;
    quant_x<<<(nquads + 255) / 256, 256>>>(x, xq, nquads);

    cudaFuncSetAttribute(gemm_sp, cudaFuncAttributeMaxDynamicSharedMemorySize, SMEM_TOTAL);
    dim3 grid(N_DIM / 256, (M + 127) / 128);    // (12, 99)
    gemm_sp<<<grid, 512, SMEM_TOTAL>>>(wc, meta, xq, bias, out, M);
}

// round 16
// speedup vs baseline: 1.0030x; 1.0030x over previous
#include <cuda_runtime.h>
#include <cuda_fp16.h>
#include <cstdint>
#include <math.h>

#define K_DIM 768
#define N_DIM 3072
#define M_MAX 12608
#define NCHUNK 12            // K / 64
#define WBLOCKS 288          // prep blocks for weight compress (3072*24/256)

// ---------------- device scratch (allocation-free rule) ----------------
__device__ __half g_xq[M_MAX * K_DIM];          // x quantized fp16 [M, K]
__device__ __half g_wc[N_DIM * NCHUNK * 32];    // compressed W fp16
__device__ uint32_t g_meta[N_DIM * 24];         // [row][k32 block]

// ---------------- PTX helpers (base-target safe) ----------------
__device__ __forceinline__ uint32_t smem_u32(const void* p) {
    uint32_t a;
    asm("{ .reg .u64 t; cvta.to.shared.u64 t, %1; cvt.u32.u64 %0, t; }" : "=r"(a) : "l"(p));
    return a;
}
__device__ __forceinline__ void cpasync16(uint32_t dst, const void* src) {
    asm volatile("cp.async.cg.shared.global [%0], [%1], 16;" :: "r"(dst), "l"(src));
}
__device__ __forceinline__ void cpasync8(uint32_t dst, const void* src) {
    asm volatile("cp.async.ca.shared.global [%0], [%1], 8;" :: "r"(dst), "l"(src));
}
#define CP_COMMIT() asm volatile("cp.async.commit_group;" ::: "memory")
__device__ __forceinline__ uint32_t lds32(uint32_t addr) {
    uint32_t v;
    asm volatile("ld.shared.b32 %0, [%1];" : "=r"(v) : "r"(addr));
    return v;
}
__device__ __forceinline__ void sts32(uint32_t addr, float v) {
    asm volatile("st.shared.f32 [%0], %1;" :: "r"(addr), "f"(v));
}
__device__ __forceinline__ float4 lds128(uint32_t addr) {
    float4 v;
    asm volatile("ld.shared.v4.f32 {%0,%1,%2,%3}, [%4];"
                 : "=f"(v.x), "=f"(v.y), "=f"(v.z), "=f"(v.w) : "r"(addr));
    return v;
}
__device__ __forceinline__ void ldsm4(uint32_t* r, uint32_t addr) {
    asm volatile("ldmatrix.sync.aligned.m8n8.x4.shared.b16 {%0,%1,%2,%3}, [%4];"
                 : "=r"(r[0]), "=r"(r[1]), "=r"(r[2]), "=r"(r[3]) : "r"(addr));
}
// sparse MMA fp16: A = m16xk32 2:4 (compressed 4 regs), B = k32xn8 (4 regs)
__device__ __forceinline__ void mma_sp_f16(float* c, const uint32_t* a,
                                           const uint32_t* b, uint32_t e) {
    asm volatile(
        "mma.sp::ordered_metadata.sync.aligned.m16n8k32.row.col.f32.f16.f16.f32 "
        "{%0,%1,%2,%3}, {%4,%5,%6,%7}, {%8,%9,%10,%11}, {%0,%1,%2,%3}, %12, 0x0;"
        : "+f"(c[0]), "+f"(c[1]), "+f"(c[2]), "+f"(c[3])
        : "r"(a[0]), "r"(a[1]), "r"(a[2]), "r"(a[3]),
          "r"(b[0]), "r"(b[1]), "r"(b[2]), "r"(b[3]), "r"(e));
}
__device__ __forceinline__ uint32_t pack_h2(float a, float b) {
    __half2 p(__float2half_rn(a), __float2half_rn(b));
    return *reinterpret_cast<uint32_t*>(&p);
}

// ---------------- fused prep: blocks [0,WBLOCKS) = W compress, rest = x quant ----------------
__global__ void prep_fused(const float* __restrict__ w, __half* __restrict__ wc,
                           uint32_t* __restrict__ meta,
                           const float* __restrict__ x, __half* __restrict__ xq,
                           int nquadsX) {
    const int b = blockIdx.x;
    if (b < WBLOCKS) {
        // ---- 2:4 prune + compress to fp16 + metadata ----
        const int idx = b * 256 + threadIdx.x;      // < 3072*24 always (288*256)
        const int row = idx / 24, kb = idx % 24;
        const float4* src = reinterpret_cast<const float4*>(w + (size_t)row * K_DIM + kb * 32);
        uint32_t hw[8], m = 0;
#pragma unroll
        for (int gq = 0; gq < 8; gq++) {
            float4 q = src[gq];
            float v[4] = {q.x, q.y, q.z, q.w};
            float a[4] = {fabsf(v[0]), fabsf(v[1]), fabsf(v[2]), fabsf(v[3])};
            int p1 = 0;
#pragma unroll
            for (int i = 1; i < 4; i++) if (a[i] < a[p1]) p1 = i;     // stable: strict <
            int p2 = (p1 == 0) ? 1 : 0;
#pragma unroll
            for (int i = 0; i < 4; i++)
                if (i != p1 && i != p2 && a[i] < a[p2]) p2 = i;
            int j0 = -1, j1 = -1;
#pragma unroll
            for (int i = 0; i < 4; i++)
                if (i != p1 && i != p2) { if (j0 < 0) j0 = i; else j1 = i; }
            m |= (uint32_t)(j0 | (j1 << 2)) << (4 * gq);
            hw[gq] = pack_h2(v[j0], v[j1]);
        }
        const int ch = kb >> 1, h = kb & 1;
        __half* dst = wc + ((size_t)row * NCHUNK + ch) * 32 + h * 16;
        uint4* d4 = reinterpret_cast<uint4*>(dst);
        d4[0] = make_uint4(hw[0], hw[1], hw[2], hw[3]);
        d4[1] = make_uint4(hw[4], hw[5], hw[6], hw[7]);
        meta[(size_t)row * 24 + kb] = m;
    } else {
        // ---- quantize x to fp16 ----
        const int g = (b - WBLOCKS) * 256 + threadIdx.x;
        if (g < nquadsX) {
            float4 v = reinterpret_cast<const float4*>(x)[g];
            reinterpret_cast<uint2*>(xq)[g] =
                make_uint2(pack_h2(v.x, v.y), pack_h2(v.z, v.w));
        }
    }
}

// ---------------- sparse GEMM  CT[N, M] = Wq(2:4) * XqT, transposed store ----------------
// CTA: 128 features x 128 tokens, 256 threads, occ 2, 4-stage cp.async (R14 pipeline).
// Warp layout (R16 change): 2 feature-warps (64f) x 4 token-warps (32t) — R15-verified
// per-warp shape; cuts CTA smem reads 80KB -> 64KB per chunk.
// stage: A(wq) 8K @0 (64B rows), B 16K @8192 (128B rows), meta 1K @24576
#define ST_A    0
#define ST_B    8192
#define ST_ME   24576
#define ST_SZ   25600
#define NSTAGE  4
#define SMEM_TOTAL (NSTAGE * ST_SZ)   // 102400 (epilogue scratch 8*8704=69632 fits)
#define EPI_STRIDE 68            // floats per token row (272B: 16B-aligned, conflict-free STS)

__global__ __launch_bounds__(256, 2)
void gemm_sp(const __half* __restrict__ Wc, const uint32_t* __restrict__ Meta,
             const __half* __restrict__ Xq,
             const float* __restrict__ bias, float* __restrict__ C, int M) {
    extern __shared__ char smem[];
    const uint32_t sbase = smem_u32(smem);
    const int tid = threadIdx.x;
    const int wid = tid >> 5, lane = tid & 31;
    const int g = lane >> 2, t4 = lane & 3;
    const int kh = lane & 1;           // meta k-half this thread supplies
    const int i_m = lane >> 3;         // ldmatrix matrix index 0..3
    const int j_m = lane & 7;          // ldmatrix row within matrix
    const int wr = wid & 1;            // feature warp: 64 features
    const int wt = wid >> 1;           // token warp: 32 tokens
    const int bn = blockIdx.x * 128;   // feature tile
    const int bt = blockIdx.y * 128;   // token tile

    auto ld_stage = [&](int t, int s) {
        const uint32_t stg = sbase + s * ST_SZ;
        // A: 8KB, 64B rows, XOR(r&3) swizzle
#pragma unroll
        for (int j = 0; j < 2; j++) {
            int i = tid + 256 * j;          // 0..511
            int r = i >> 2, c = i & 3;
            uint32_t sw = (uint32_t)(r * 64 + ((c ^ (r & 3)) << 4));
            cpasync16(stg + ST_A + sw, Wc + ((size_t)(bn + r) * NCHUNK + t) * 32 + c * 8);
        }
        // B: 16KB, 128B rows, XOR(r&7) swizzle
#pragma unroll
        for (int j = 0; j < 4; j++) {
            int i = tid + 256 * j;          // 0..1023
            int r = i >> 3, c = i & 7;
            uint32_t sw = (uint32_t)(r * 128 + ((c ^ (r & 7)) << 4));
            int tok = bt + r; if (tok > M - 1) tok = M - 1;
            cpasync16(stg + ST_B + sw, Xq + (size_t)tok * K_DIM + t * 64 + c * 8);
        }
        if (tid < 128)
            cpasync8(stg + ST_ME + tid * 8, Meta + (size_t)(bn + tid) * 24 + t * 2);
        CP_COMMIT();
    };

    float acc[4][4][4];
#pragma unroll
    for (int mt = 0; mt < 4; mt++)
#pragma unroll
        for (int nt = 0; nt < 4; nt++)
#pragma unroll
            for (int q = 0; q < 4; q++) acc[mt][nt][q] = 0.0f;

    // prologue: 3 chunks in flight
    ld_stage(0, 0);
    ld_stage(1, 1);
    ld_stage(2, 2);

    for (int t = 0; t < NCHUNK; t++) {
        if (t <= NCHUNK - 3)      asm volatile("cp.async.wait_group 2;" ::: "memory");
        else if (t == NCHUNK - 2) asm volatile("cp.async.wait_group 1;" ::: "memory");
        else                      asm volatile("cp.async.wait_group 0;" ::: "memory");
        // barrier also orders: all warps done computing chunk t-1 before ld_stage below
        // overwrites stage (t+3)&3 == (t-1)&3.
        __syncthreads();

        const uint32_t stg = sbase + (t & (NSTAGE - 1)) * ST_SZ;
#pragma unroll
        for (int h = 0; h < 2; h++) {                 // two k32 steps per chunk
            uint32_t e[4], aq[4][4];
#pragma unroll
            for (int mt = 0; mt < 4; mt++) {
                const int rbase = wr * 64 + mt * 16;
                // metadata (m16n8k32, sel 0): T_even k0..15 / T_odd k16..31 of rows g, g+8
                const uint32_t m_a = lds32(stg + ST_ME + (rbase + g) * 8 + h * 4);
                const uint32_t m_b = lds32(stg + ST_ME + (rbase + g + 8) * 8 + h * 4);
                e[mt] = ((m_a >> (16 * kh)) & 0xFFFFu) | (((m_b >> (16 * kh)) & 0xFFFFu) << 16);
                // A fragment via ldmatrix.x4 (64B rows, 4 octets: step h uses octets 2h, 2h+1)
                const int arow = rbase + ((i_m & 1) << 3) + j_m;
                const int oct = 2 * h + (i_m >> 1);
                ldsm4(aq[mt], stg + ST_A + arow * 64 + (uint32_t)((oct ^ (arow & 3)) << 4));
            }
#pragma unroll
            for (int nt = 0; nt < 4; nt++) {
                // B fragment via ldmatrix.x4: matrix i = k-octet (4h+i) of 8 token rows
                const int tok = wt * 32 + nt * 8 + j_m;
                const uint32_t sw = (uint32_t)(((4 * h + i_m) ^ (tok & 7)) << 4);
                uint32_t bq[4];
                ldsm4(bq, stg + ST_B + tok * 128 + sw);
#pragma unroll
                for (int mt = 0; mt < 4; mt++)
                    mma_sp_f16(acc[mt][nt], aq[mt], bq, e[mt]);
            }
        }
        if (t + 3 < NCHUNK) ld_stage(t + 3, (t + 3) & (NSTAGE - 1));
    }

    // ---- epilogue: bias + smem transpose (CT frag -> C[token][feature]) ----  (R15-verified shape)
    __syncthreads();   // done reading stages; reuse smem
    float bias_v[4][2];
#pragma unroll
    for (int mt = 0; mt < 4; mt++) {
        const int f = bn + wr * 64 + mt * 16 + g;
        bias_v[mt][0] = __ldg(bias + f);
        bias_v[mt][1] = __ldg(bias + f + 8);
    }
    // warp-private region: 32 tokens x EPI_STRIDE floats (8704 B/warp, 69632 total)
    const uint32_t wb = sbase + wid * (32 * EPI_STRIDE * 4);
#pragma unroll
    for (int mt = 0; mt < 4; mt++)
#pragma unroll
        for (int nt = 0; nt < 4; nt++) {
            const int tokL = nt * 8 + 2 * t4;
            const int fL = mt * 16 + g;
            const uint32_t a0 = wb + (uint32_t)(tokL * EPI_STRIDE + fL) * 4;
            sts32(a0,                        acc[mt][nt][0] + bias_v[mt][0]);
            sts32(a0 + EPI_STRIDE * 4,       acc[mt][nt][1] + bias_v[mt][0]);  // token+1
            sts32(a0 + 32,                   acc[mt][nt][2] + bias_v[mt][1]);  // feat+8
            sts32(a0 + EPI_STRIDE * 4 + 32,  acc[mt][nt][3] + bias_v[mt][1]);
        }
    __syncwarp();
#pragma unroll
    for (int it = 0; it < 4; it++) {
        const int tokL = it * 8 + g;
        const int tokG = bt + wt * 32 + tokL;
        if (tokG < M) {
#pragma unroll
            for (int j = 0; j < 4; j++) {
                const int fl = t4 * 4 + j * 16;
                float4 v = lds128(wb + (uint32_t)(tokL * EPI_STRIDE + fl) * 4);
                *reinterpret_cast<float4*>(C + (size_t)tokG * N_DIM + bn + wr * 64 + fl) = v;
            }
        }
    }
}

// ---------------------------------------------------------------------------
extern "C" void kernel_launch(void* const* d_in, const int* in_sizes, int n_in,
                              void* d_out, int out_size) {
    const float* x    = (const float*)d_in[0];  // [M, 768]
    const float* w    = (const float*)d_in[1];  // [3072, 768]
    const float* bias = (const float*)d_in[2];  // [3072]
    float* out        = (float*)d_out;          // [M, 3072]
    (void)n_in; (void)out_size;

    const int M = in_sizes[0] / K_DIM;          // 12608

    __half *xq, *wc;
    uint32_t* meta;
    cudaGetSymbolAddress((void**)&xq, g_xq);
    cudaGetSymbolAddress((void**)&wc, g_wc);
    cudaGetSymbolAddress((void**)&meta, g_meta);

    const int nquadsX = (M * K_DIM) / 4;
    const int qblocks = (nquadsX + 255) / 256;
    prep_fused<<<WBLOCKS + qblocks, 256>>>(w, wc, meta, x, xq, nquadsX);

    cudaFuncSetAttribute(gemm_sp, cudaFuncAttributeMaxDynamicSharedMemorySize, SMEM_TOTAL);
    dim3 grid(N_DIM / 128, (M + 127) / 128);    // (24, 99)
    gemm_sp<<<grid, 256, SMEM_TOTAL>>>(wc, meta, xq, bias, out, M);
}

// round 17
// speedup vs baseline: 1.0645x; 1.0613x over previous
#include <cuda_runtime.h>
#include <cuda_fp16.h>
#include <cstdint>
#include <math.h>

#define K_DIM 768
#define N_DIM 3072
#define M_MAX 12608
#define NCHUNK 12            // K / 64
#define WBLOCKS 288          // prep blocks for weight compress (3072*24/256)

// ---------------- device scratch (allocation-free rule) ----------------
__device__ __half g_xq[M_MAX * K_DIM];          // x quantized fp16 [M, K]
__device__ __half g_wc[N_DIM * NCHUNK * 32];    // compressed W fp16
__device__ uint32_t g_meta[N_DIM * 24];         // [row][k32 block]

// ---------------- PTX helpers (base-target safe) ----------------
__device__ __forceinline__ uint32_t smem_u32(const void* p) {
    uint32_t a;
    asm("{ .reg .u64 t; cvta.to.shared.u64 t, %1; cvt.u32.u64 %0, t; }" : "=r"(a) : "l"(p));
    return a;
}
__device__ __forceinline__ void cpasync16(uint32_t dst, const void* src) {
    asm volatile("cp.async.cg.shared.global [%0], [%1], 16;" :: "r"(dst), "l"(src));
}
__device__ __forceinline__ void cpasync8(uint32_t dst, const void* src) {
    asm volatile("cp.async.ca.shared.global [%0], [%1], 8;" :: "r"(dst), "l"(src));
}
#define CP_COMMIT() asm volatile("cp.async.commit_group;" ::: "memory")
__device__ __forceinline__ uint32_t lds32(uint32_t addr) {
    uint32_t v;
    asm volatile("ld.shared.b32 %0, [%1];" : "=r"(v) : "r"(addr));
    return v;
}
__device__ __forceinline__ void sts32(uint32_t addr, float v) {
    asm volatile("st.shared.f32 [%0], %1;" :: "r"(addr), "f"(v));
}
__device__ __forceinline__ float4 lds128(uint32_t addr) {
    float4 v;
    asm volatile("ld.shared.v4.f32 {%0,%1,%2,%3}, [%4];"
                 : "=f"(v.x), "=f"(v.y), "=f"(v.z), "=f"(v.w) : "r"(addr));
    return v;
}
__device__ __forceinline__ void ldsm4(uint32_t* r, uint32_t addr) {
    asm volatile("ldmatrix.sync.aligned.m8n8.x4.shared.b16 {%0,%1,%2,%3}, [%4];"
                 : "=r"(r[0]), "=r"(r[1]), "=r"(r[2]), "=r"(r[3]) : "r"(addr));
}
// sparse MMA fp16: A = m16xk32 2:4 (compressed 4 regs), B = k32xn8 (4 regs)
__device__ __forceinline__ void mma_sp_f16(float* c, const uint32_t* a,
                                           const uint32_t* b, uint32_t e) {
    asm volatile(
        "mma.sp::ordered_metadata.sync.aligned.m16n8k32.row.col.f32.f16.f16.f32 "
        "{%0,%1,%2,%3}, {%4,%5,%6,%7}, {%8,%9,%10,%11}, {%0,%1,%2,%3}, %12, 0x0;"
        : "+f"(c[0]), "+f"(c[1]), "+f"(c[2]), "+f"(c[3])
        : "r"(a[0]), "r"(a[1]), "r"(a[2]), "r"(a[3]),
          "r"(b[0]), "r"(b[1]), "r"(b[2]), "r"(b[3]), "r"(e));
}
__device__ __forceinline__ uint32_t pack_h2(float a, float b) {
    __half2 p(__float2half_rn(a), __float2half_rn(b));
    return *reinterpret_cast<uint32_t*>(&p);
}

// ---------------- fused prep: blocks [0,WBLOCKS) = W compress, rest = x quant ----------------
__global__ void prep_fused(const float* __restrict__ w, __half* __restrict__ wc,
                           uint32_t* __restrict__ meta,
                           const float* __restrict__ x, __half* __restrict__ xq,
                           int nquadsX) {
    const int b = blockIdx.x;
    if (b < WBLOCKS) {
        // ---- 2:4 prune + compress to fp16 + metadata ----
        const int idx = b * 256 + threadIdx.x;      // < 3072*24 always (288*256)
        const int row = idx / 24, kb = idx % 24;
        const float4* src = reinterpret_cast<const float4*>(w + (size_t)row * K_DIM + kb * 32);
        uint32_t hw[8], m = 0;
#pragma unroll
        for (int gq = 0; gq < 8; gq++) {
            float4 q = src[gq];
            float v[4] = {q.x, q.y, q.z, q.w};
            float a[4] = {fabsf(v[0]), fabsf(v[1]), fabsf(v[2]), fabsf(v[3])};
            int p1 = 0;
#pragma unroll
            for (int i = 1; i < 4; i++) if (a[i] < a[p1]) p1 = i;     // stable: strict <
            int p2 = (p1 == 0) ? 1 : 0;
#pragma unroll
            for (int i = 0; i < 4; i++)
                if (i != p1 && i != p2 && a[i] < a[p2]) p2 = i;
            int j0 = -1, j1 = -1;
#pragma unroll
            for (int i = 0; i < 4; i++)
                if (i != p1 && i != p2) { if (j0 < 0) j0 = i; else j1 = i; }
            m |= (uint32_t)(j0 | (j1 << 2)) << (4 * gq);
            hw[gq] = pack_h2(v[j0], v[j1]);
        }
        const int ch = kb >> 1, h = kb & 1;
        __half* dst = wc + ((size_t)row * NCHUNK + ch) * 32 + h * 16;
        uint4* d4 = reinterpret_cast<uint4*>(dst);
        d4[0] = make_uint4(hw[0], hw[1], hw[2], hw[3]);
        d4[1] = make_uint4(hw[4], hw[5], hw[6], hw[7]);
        meta[(size_t)row * 24 + kb] = m;
    } else {
        // ---- quantize x to fp16 ----
        const int g = (b - WBLOCKS) * 256 + threadIdx.x;
        if (g < nquadsX) {
            float4 v = reinterpret_cast<const float4*>(x)[g];
            reinterpret_cast<uint2*>(xq)[g] =
                make_uint2(pack_h2(v.x, v.y), pack_h2(v.z, v.w));
        }
    }
}

// ---------------- sparse GEMM  CT[N, M] = Wq(2:4) * XqT, transposed store ----------------
// CTA: 128 features x 128 tokens, 256 threads, occ 2, 4-stage cp.async.
// Warp layout (R14-verbatim, proven no-spill): 4 feature-warps (32f) x 2 token-warps (64t).
// ld_stage hoisted before compute (same ordering guarantees, earlier load issue).
// stage: A(wq) 8K @0 (64B rows), B 16K @8192 (128B rows), meta 1K @24576
#define ST_A    0
#define ST_B    8192
#define ST_ME   24576
#define ST_SZ   25600
#define NSTAGE  4
#define SMEM_TOTAL (NSTAGE * ST_SZ)   // 102400 (epilogue scratch 8*9216=73728 fits)
#define EPI_STRIDE 36            // floats per token row (144B: 16B-aligned for lds128)

__global__ __launch_bounds__(256, 2)
void gemm_sp(const __half* __restrict__ Wc, const uint32_t* __restrict__ Meta,
             const __half* __restrict__ Xq,
             const float* __restrict__ bias, float* __restrict__ C, int M) {
    extern __shared__ char smem[];
    const uint32_t sbase = smem_u32(smem);
    const int tid = threadIdx.x;
    const int wid = tid >> 5, lane = tid & 31;
    const int g = lane >> 2, t4 = lane & 3;
    const int kh = lane & 1;           // meta k-half this thread supplies
    const int i_m = lane >> 3;         // ldmatrix matrix index 0..3
    const int j_m = lane & 7;          // ldmatrix row within matrix
    const int wr = wid & 3;            // feature warp: 32 features
    const int wt = wid >> 2;           // token warp: 64 tokens
    const int bn = blockIdx.x * 128;   // feature tile
    const int bt = blockIdx.y * 128;   // token tile

    auto ld_stage = [&](int t, int s) {
        const uint32_t stg = sbase + s * ST_SZ;
        // A: 8KB, 64B rows, XOR(r&3) swizzle
#pragma unroll
        for (int j = 0; j < 2; j++) {
            int i = tid + 256 * j;          // 0..511
            int r = i >> 2, c = i & 3;
            uint32_t sw = (uint32_t)(r * 64 + ((c ^ (r & 3)) << 4));
            cpasync16(stg + ST_A + sw, Wc + ((size_t)(bn + r) * NCHUNK + t) * 32 + c * 8);
        }
        // B: 16KB, 128B rows, XOR(r&7) swizzle
#pragma unroll
        for (int j = 0; j < 4; j++) {
            int i = tid + 256 * j;          // 0..1023
            int r = i >> 3, c = i & 7;
            uint32_t sw = (uint32_t)(r * 128 + ((c ^ (r & 7)) << 4));
            int tok = bt + r; if (tok > M - 1) tok = M - 1;
            cpasync16(stg + ST_B + sw, Xq + (size_t)tok * K_DIM + t * 64 + c * 8);
        }
        if (tid < 128)
            cpasync8(stg + ST_ME + tid * 8, Meta + (size_t)(bn + tid) * 24 + t * 2);
        CP_COMMIT();
    };

    float acc[2][8][4];
#pragma unroll
    for (int mt = 0; mt < 2; mt++)
#pragma unroll
        for (int nt = 0; nt < 8; nt++)
#pragma unroll
            for (int q = 0; q < 4; q++) acc[mt][nt][q] = 0.0f;

    // prologue: 3 chunks in flight
    ld_stage(0, 0);
    ld_stage(1, 1);
    ld_stage(2, 2);

    for (int t = 0; t < NCHUNK; t++) {
        if (t <= NCHUNK - 3)      asm volatile("cp.async.wait_group 2;" ::: "memory");
        else if (t == NCHUNK - 2) asm volatile("cp.async.wait_group 1;" ::: "memory");
        else                      asm volatile("cp.async.wait_group 0;" ::: "memory");
        // barrier also orders: all warps done computing chunk t-1 before ld_stage below
        // overwrites stage (t+3)&3 == (t-1)&3.
        __syncthreads();

        // issue next chunk's loads FIRST (hides global latency behind this chunk's math)
        if (t + 3 < NCHUNK) ld_stage(t + 3, (t + 3) & (NSTAGE - 1));

        const uint32_t stg = sbase + (t & (NSTAGE - 1)) * ST_SZ;
#pragma unroll
        for (int h = 0; h < 2; h++) {                 // two k32 steps per chunk
            uint32_t e[2], aq[2][4];
#pragma unroll
            for (int mt = 0; mt < 2; mt++) {
                const int rbase = wr * 32 + mt * 16;
                // metadata (m16n8k32, sel 0): T_even k0..15 / T_odd k16..31 of rows g, g+8
                const uint32_t m_a = lds32(stg + ST_ME + (rbase + g) * 8 + h * 4);
                const uint32_t m_b = lds32(stg + ST_ME + (rbase + g + 8) * 8 + h * 4);
                e[mt] = ((m_a >> (16 * kh)) & 0xFFFFu) | (((m_b >> (16 * kh)) & 0xFFFFu) << 16);
                // A fragment via ldmatrix.x4 (64B rows, 4 octets: step h uses octets 2h, 2h+1)
                const int arow = rbase + ((i_m & 1) << 3) + j_m;
                const int oct = 2 * h + (i_m >> 1);
                ldsm4(aq[mt], stg + ST_A + arow * 64 + (uint32_t)((oct ^ (arow & 3)) << 4));
            }
#pragma unroll
            for (int nt = 0; nt < 8; nt++) {
                // B fragment via ldmatrix.x4: matrix i = k-octet (4h+i) of 8 token rows
                const int tok = wt * 64 + nt * 8 + j_m;
                const uint32_t sw = (uint32_t)(((4 * h + i_m) ^ (tok & 7)) << 4);
                uint32_t bq[4];
                ldsm4(bq, stg + ST_B + tok * 128 + sw);
#pragma unroll
                for (int mt = 0; mt < 2; mt++)
                    mma_sp_f16(acc[mt][nt], aq[mt], bq, e[mt]);
            }
        }
    }

    // ---- epilogue: bias + smem transpose (CT frag -> C[token][feature]) ----  (R14 verbatim)
    __syncthreads();   // done reading stages; reuse smem
    float bias_v[2][2];
#pragma unroll
    for (int mt = 0; mt < 2; mt++) {
        const int f = bn + wr * 32 + mt * 16 + g;
        bias_v[mt][0] = __ldg(bias + f);
        bias_v[mt][1] = __ldg(bias + f + 8);
    }
    // warp-private region: 64 tokens x EPI_STRIDE floats (144B rows)
    const uint32_t wb = sbase + wid * (64 * EPI_STRIDE * 4);   // 9216 B/warp, 73728 total
#pragma unroll
    for (int mt = 0; mt < 2; mt++)
#pragma unroll
        for (int nt = 0; nt < 8; nt++) {
            const int tokL = nt * 8 + 2 * t4;
            const int fL = mt * 16 + g;
            const uint32_t a0 = wb + (uint32_t)(tokL * EPI_STRIDE + fL) * 4;
            sts32(a0,                        acc[mt][nt][0] + bias_v[mt][0]);
            sts32(a0 + EPI_STRIDE * 4,       acc[mt][nt][1] + bias_v[mt][0]);  // token+1
            sts32(a0 + 32,                   acc[mt][nt][2] + bias_v[mt][1]);  // feat+8
            sts32(a0 + EPI_STRIDE * 4 + 32,  acc[mt][nt][3] + bias_v[mt][1]);
        }
    __syncwarp();
#pragma unroll
    for (int it = 0; it < 8; it++) {
        const int tokL = it * 8 + g;
        const int tokG = bt + wt * 64 + tokL;
        if (tokG < M) {
#pragma unroll
            for (int j = 0; j < 2; j++) {
                const int fl = t4 * 4 + j * 16;
                float4 v = lds128(wb + (uint32_t)(tokL * EPI_STRIDE + fl) * 4);
                *reinterpret_cast<float4*>(C + (size_t)tokG * N_DIM + bn + wr * 32 + fl) = v;
            }
        }
    }
}

// ---------------------------------------------------------------------------
extern "C" void kernel_launch(void* const* d_in, const int* in_sizes, int n_in,
                              void* d_out, int out_size) {
    const float* x    = (const float*)d_in[0];  // [M, 768]
    const float* w    = (const float*)d_in[1];  // [3072, 768]
    const float* bias = (const float*)d_in[2];  // [3072]
    float* out        = (float*)d_out;          // [M, 3072]
    (void)n_in; (void)out_size;

    const int M = in_sizes[0] / K_DIM;          // 12608

    __half *xq, *wc;
    uint32_t* meta;
    cudaGetSymbolAddress((void**)&xq, g_xq);
    cudaGetSymbolAddress((void**)&wc, g_wc);
    cudaGetSymbolAddress((void**)&meta, g_meta);

    const int nquadsX = (M * K_DIM) / 4;
    const int qblocks = (nquadsX + 255) / 256;
    prep_fused<<<WBLOCKS + qblocks, 256>>>(w, wc, meta, x, xq, nquadsX);

    cudaFuncSetAttribute(gemm_sp, cudaFuncAttributeMaxDynamicSharedMemorySize, SMEM_TOTAL);
    dim3 grid(N_DIM / 128, (M + 127) / 128);    // (24, 99)
    gemm_sp<<<grid, 256, SMEM_TOTAL>>>(wc, meta, xq, bias, out, M);
}